// round 16
// baseline (speedup 1.0000x reference)
#include <cuda_runtime.h>
#include <math.h>

#define T_NO   200
#define SUBN   20
#define E_NOC  2000
#define I_NOC  500
#define T_DATA 10000
#define COS_NO 17
#define BW     32                       // recurrence block size
#define NBLK   ((T_DATA + BW - 1) / BW) // 313

// ---------------- device scratch (static allocation only) ----------------
__device__ float g_se[T_DATA * SUBN];
__device__ float g_si[T_DATA * SUBN];
__device__ float g_syn[T_DATA * SUBN];    // filtered drive + Theta folded in
__device__ float g_sv[T_DATA * SUBN];     // raw pre-activation
__device__ float g_ek[SUBN * T_NO];
__device__ float g_ik[SUBN * T_NO];
__device__ float g_spkk[SUBN * T_NO];
__device__ float g_histk[SUBN * T_NO];
__device__ float g_lut[SUBN * 1024];      // byte LUT (leader): [s][k=0..3][256], taps 1+8k+j (1..32)
__device__ float g_lutm[SUBN * 128];      // nibble LUT (leader mid): [s][i=0..7][16], taps 33+4i+j (<=63)
__device__ float g_lutn[SUBN * 800];      // nibble LUT (gathers): [s][i=0..49][n=0..15], taps 4i+j
__device__ int   g_idx_e[E_NOC];
__device__ int   g_idx_i[I_NOC];

// ---------------- K0: indices + kernels + LUTs + filter output ----------------
__global__ void prep_kernel(const float* __restrict__ C_syn_e,
                            const float* __restrict__ C_syn_i,
                            const float* __restrict__ Tau_syn,
                            const float* __restrict__ Delta_syn,
                            const float* __restrict__ W_syn,
                            const float* __restrict__ Tau_spk,
                            const float* __restrict__ W_spk,
                            const float* __restrict__ W_hist,
                            float* __restrict__ filt_out)
{
    int tid = threadIdx.x;
    int nt  = blockDim.x;

    for (int e = tid; e < E_NOC; e += nt) {
        int k = 0;
        for (int s = 0; s < SUBN; s++)
            if (C_syn_e[s * E_NOC + e] > 0.5f) k = s;
        g_idx_e[e] = k;
    }
    for (int e = tid; e < I_NOC; e += nt) {
        int k = 0;
        for (int s = 0; s < SUBN; s++)
            if (C_syn_i[s * I_NOC + e] > 0.5f) k = s;
        g_idx_i[e] = k;
    }

    const float PIF = 3.14159265358979323846f;
    for (int i = tid; i < SUBN * T_NO; i += nt) {
        int s = i / T_NO;
        int m = i % T_NO;
        float mf = (float)m;

        float te  = fmaxf(mf - expf(Delta_syn[s * 2 + 0]), 0.0f);
        float tte = te / expf(Tau_syn[s * 2 + 0]);
        float ek  = tte * expf(-tte) * expf(W_syn[s * 2 + 0]);

        float td  = fmaxf(mf - expf(Delta_syn[s * 2 + 1]), 0.0f);
        float tti = td / expf(Tau_syn[s * 2 + 1]);
        float ik  = -tti * expf(-tti) * expf(W_syn[s * 2 + 1]);

        float tts = mf / expf(Tau_spk[s]);
        float sk  = tts * expf(-tts) * expf(W_spk[s]);

        float raw = 4.0f * logf(mf + 1.0f);
        float hk  = 0.0f;
        for (int c = 0; c < COS_NO; c++) {
            float phi = (PIF * 0.5f) * (float)c;
            if (raw >= phi - PIF && raw <= phi + PIF)
                hk += W_hist[s * COS_NO + c] * (0.5f * cosf(raw - phi) + 0.5f);
        }

        g_ek[i]    = ek;
        g_ik[i]    = ik;
        g_spkk[i]  = sk;
        g_histk[i] = hk;

        filt_out[(0 * SUBN + s) * T_NO + m] = ek;
        filt_out[(1 * SUBN + s) * T_NO + m] = ik;
        filt_out[(2 * SUBN + s) * T_NO + m] = sk;
        filt_out[(3 * SUBN + s) * T_NO + m] = hk;
    }
    __syncthreads();

    // leader byte LUT: lut[s][k][b] = sum_j bit_j(b)*histk[s][1+8k+j]  (taps 1..32)
    for (int i = tid; i < SUBN * 1024; i += nt) {
        int s = i >> 10;
        int k = (i >> 8) & 3;
        int b = i & 255;
        float v = 0.0f;
        for (int j = 0; j < 8; j++)
            if (b & (1 << j)) v += g_histk[s * T_NO + 1 + 8 * k + j];
        g_lut[i] = v;
    }
    // leader mid nibble LUT: lutm[s][i][n] = sum_j bit_j(n)*histk[s][33+4i+j], taps<=63
    for (int i = tid; i < SUBN * 128; i += nt) {
        int s  = i >> 7;
        int ii = (i >> 4) & 7;
        int n  = i & 15;
        float v = 0.0f;
        for (int j = 0; j < 4; j++) {
            int m = 33 + 4 * ii + j;
            if (m <= 63 && ((n >> j) & 1)) v += g_histk[s * T_NO + m];
        }
        g_lutm[i] = v;
    }
    // gather nibble LUT: lutn[s][i][n] = sum_j bit_j(n) * histk[s][4i+j]
    for (int i = tid; i < SUBN * 800; i += nt) {
        int s = i / 800;
        int r = i % 800;
        int k = r >> 4;
        int n = r & 15;
        float v = 0.0f;
        for (int j = 0; j < 4; j++) {
            int m = 4 * k + j;
            if (m < T_NO && ((n >> j) & 1)) v += g_histk[s * T_NO + m];
        }
        g_lutn[i] = v;
    }
}

// ---------------- K1: one-hot scatter-sum ----------------
__global__ void agg_kernel(const float* __restrict__ S_e,
                           const float* __restrict__ S_i)
{
    __shared__ float acc_e[SUBN];
    __shared__ float acc_i[SUBN];
    int t   = blockIdx.x;
    int tid = threadIdx.x;
    if (tid < SUBN) { acc_e[tid] = 0.0f; acc_i[tid] = 0.0f; }
    __syncthreads();

    const float* re = S_e + (size_t)t * E_NOC;
    for (int e = tid; e < E_NOC; e += blockDim.x) {
        float v = re[e];
        if (v != 0.0f) atomicAdd(&acc_e[g_idx_e[e]], v);
    }
    const float* ri = S_i + (size_t)t * I_NOC;
    for (int e = tid; e < I_NOC; e += blockDim.x) {
        float v = ri[e];
        if (v != 0.0f) atomicAdd(&acc_i[g_idx_i[e]], v);
    }
    __syncthreads();
    if (tid < SUBN) {
        g_se[t * SUBN + tid] = acc_e[tid];
        g_si[t * SUBN + tid] = acc_i[tid];
    }
}

// ---------------- K2: causal FIR, smem-staged, Theta folded in ----------------
#define CONV_TS 256
#define CONV_THREADS 512
#define CONV_ROWS (CONV_TS + T_NO)
#define CONV_SMEM_FLOATS (4000 + 4000 + CONV_ROWS*SUBN + CONV_ROWS*SUBN)

__global__ void __launch_bounds__(CONV_THREADS, 1)
conv_kernel(const float* __restrict__ Theta)
{
    extern __shared__ float cs[];
    float* ek   = cs;
    float* ik   = ek + 4000;
    float* se_s = ik + 4000;
    float* si_s = se_s + CONV_ROWS * SUBN;

    int tid = threadIdx.x;
    int t0  = blockIdx.x * CONV_TS;

    for (int i = tid; i < SUBN * T_NO; i += CONV_THREADS) {
        ek[i] = g_ek[i];
        ik[i] = g_ik[i];
    }
    for (int i = tid; i < CONV_ROWS * SUBN; i += CONV_THREADS) {
        int r  = i / SUBN;
        int s  = i % SUBN;
        int tg = t0 - T_NO + r;
        float ve = 0.0f, vi = 0.0f;
        if (tg >= 0 && tg < T_DATA) {
            ve = g_se[tg * SUBN + s];
            vi = g_si[tg * SUBN + s];
        }
        se_s[i] = ve;
        si_s[i] = vi;
    }
    __syncthreads();

    for (int wi = tid; wi < CONV_TS * SUBN; wi += CONV_THREADS) {
        int tt = t0 + wi / SUBN;
        int s  = wi % SUBN;
        if (tt >= T_DATA) continue;
        int mmax = min(T_NO, tt);
        int base = ((tt - t0 + T_NO - 1) * SUBN) + s;
        const float* eks = ek + s * T_NO;
        const float* iks = ik + s * T_NO;
        float a0 = 0.0f, a1 = 0.0f;
        for (int m = 0; m < mmax; m++) {
            int ai = base - m * SUBN;
            a0 = fmaf(eks[m], se_s[ai], a0);
            a1 = fmaf(iks[m], si_s[ai], a1);
        }
        g_syn[tt * SUBN + s] = a0 + a1 + Theta[s];
    }
}

// ---------------- K3: blocked recurrence (R14 structure, mid taps in leader) --
// Leader (warp 13, SMSP1): taps 0..63 in-register (zmask + zprev; byte LUT
// taps 1..32, lutm taps 33..63, tap 0 register FMA), lookahead 2; matvec via
// double-buffered shq. Phase A: pure fold Etot = Hfar + synb. Far gathers on
// the 10 non-SMSP1 warps, feeding Hfar one block ahead. Two barriers/block.
#define RECUR_THREADS 448               // 14 warps; warp 13 = leader
#define EPITCH 21
#define LPITCH 1025                     // byte LUT pitch (odd)
#define MPITCH 129                      // mid nibble LUT pitch (odd)
#define NPITCH 801                      // gather nibble LUT pitch (odd)
#define BWPITCH 17
#define ALIGN4(x) (((x) + 3) & ~3)      // 16-byte alignment for float4 regions

#define OFF_LUT   0                                   // [20][1025]
#define OFF_LUTM  (OFF_LUT + SUBN*LPITCH)             // [20][129]
#define OFF_LUTN  (OFF_LUTM + SUBN*MPITCH)            // [20][801]
#define OFF_ETOT  ALIGN4(OFF_LUTN + SUBN*NPITCH)      // [33][21] (1 pad row)
#define OFF_HFAR  (OFF_ETOT + (BW+1)*EPITCH)          // [32][21]
#define OFF_SYNB  (OFF_HFAR + BW*EPITCH)              // [32][21]
#define OFF_SHQ   ALIGN4(OFF_SYNB + BW*EPITCH)        // [2][32] double-buffered q (float4-read!)
#define OFF_BWR   (OFF_SHQ + 64)                      // [20][17] u32 ring
#define RECUR_SMEM_FLOATS (OFF_BWR + SUBN*BWPITCH)

__global__ void __launch_bounds__(RECUR_THREADS, 1)
recur_kernel(const float* __restrict__ C_den,
             const float* __restrict__ Tau_spk,
             const float* __restrict__ W_spk)
{
    extern __shared__ float sm[];
    float*    lut  = sm + OFF_LUT;
    float*    lutm = sm + OFF_LUTM;
    float*    lutn = sm + OFF_LUTN;
    float*    Etot = sm + OFF_ETOT;
    float*    Hfar = sm + OFF_HFAR;
    float*    synb = sm + OFF_SYNB;
    float*    shq  = sm + OFF_SHQ;
    unsigned* bwr  = (unsigned*)(sm + OFF_BWR);

    int tid  = threadIdx.x;
    int w    = tid >> 5;
    int lane = tid & 31;

    // ---- init smem ----
    for (int i = tid; i < SUBN * 1024; i += RECUR_THREADS)
        lut[(i >> 10) * LPITCH + (i & 1023)] = g_lut[i];
    for (int i = tid; i < SUBN * 128; i += RECUR_THREADS)
        lutm[(i >> 7) * MPITCH + (i & 127)] = g_lutm[i];
    for (int i = tid; i < SUBN * 800; i += RECUR_THREADS)
        lutn[(i / 800) * NPITCH + (i % 800)] = g_lutn[i];
    for (int i = tid; i < (BW + 1) * EPITCH; i += RECUR_THREADS) Etot[i] = 0.0f;
    for (int i = tid; i < BW * EPITCH; i += RECUR_THREADS) {
        int r = i / EPITCH, c = i % EPITCH;
        Hfar[i] = 0.0f;
        synb[i] = (c < SUBN) ? g_syn[r * SUBN + c] : 0.0f;   // block-0 rows
    }
    if (tid < 64) shq[tid] = 0.0f;
    for (int i = tid; i < SUBN * BWPITCH; i += RECUR_THREADS) bwr[i] = 0u;

    // ---- leader registers ----
    float rr = 0, cc = 0, U = 0, V = 0;
    float pendA = 0, pendB = 0;        // LUT sums (taps 1..63), lookahead 2
    float Gcur = 0;                    // C_den@q contribution
    float z1 = 0, kh0 = 0;             // tap m=0
    unsigned zmask = 0, zprev = 0;
    float cd[SUBN];
    #pragma unroll
    for (int j = 0; j < SUBN; j++) cd[j] = 0.0f;
    if (w == 13 && lane < SUBN) {
        rr  = expf(-expf(-Tau_spk[lane]));
        cc  = expf(W_spk[lane] - Tau_spk[lane]);
        kh0 = g_histk[lane * T_NO + 0];
        #pragma unroll
        for (int j = 0; j < SUBN; j++) cd[j] = C_den[lane * SUBN + j];
    }

    // far-gather assignment: 10 warps not on the leader's SMSP
    bool isFar = (w < 13) && (w != 1) && (w != 5) && (w != 9);
    int fpos = w - (w > 1) - (w > 5) - (w > 9);     // 0..9 for far warps

    // staging row assignment (rows of the NEXT block's syn) — all 13 warps
    int r0 = w, r1 = w + 13, r2 = w + 26;   // r2 valid only for w<6
    __syncthreads();

    int p  = lane;                       // output index within block
    bool o = (p == 0);
    unsigned sh = (unsigned)((32 - p) & 31);

    for (int blk = 0; blk < NBLK; blk++) {
        int T0 = blk * BW;

        // ---------- phase A: fold Etot = Hfar + synb ----------
        if (w < 13) {
            for (int pass = w; pass < SUBN; pass += 13) {
                int oo = p * EPITCH + pass;
                Etot[oo] = Hfar[oo] + synb[oo];
            }
        }
        __syncthreads();

        // ---------- phase B ----------
        if (w == 13) {
            // leader: 32 sequential steps
            float ecur = (lane < SUBN) ? Etot[lane] : 0.0f;
            #pragma unroll 4
            for (int pp2 = 0; pp2 < BW / 2; pp2++) {
                #pragma unroll
                for (int half = 0; half < 2; half++) {
                    int pp = pp2 * 2 + half;
                    int t  = T0 + pp;
                    float pendC = (half == 0) ? pendA : pendB;
                    float zf = 0.0f;
                    if (lane < SUBN) {
                        // consume (prepared >= 1 step ago)
                        float sv = fmaf(kh0, z1, (ecur + Gcur) + pendC);
                        if (t < T_DATA) g_sv[t * SUBN + lane] = sv;
                        unsigned zb = (sv > 0.0f) ? 1u : 0u;
                        unsigned oldb = zmask >> 31;
                        zmask = (zmask << 1) | zb;
                        zprev = (zprev << 1) | oldb;
                        zf = (float)zb;
                        // prepare taps 1..63 for step t+2 (post-update words)
                        const float* lp = &lut[lane * LPITCH];
                        float n0 = lp[        (zmask & 255u)];
                        float n1 = lp[256 + ((zmask >> 8)  & 255u)];
                        float n2 = lp[512 + ((zmask >> 16) & 255u)];
                        float n3 = lp[768 +  (zmask >> 24)];
                        const float* lm = &lutm[lane * MPITCH];
                        float m0 = lm[0   +  (zprev        & 15u)]
                                 + lm[16  + ((zprev >> 4)  & 15u)];
                        float m1 = lm[32  + ((zprev >> 8)  & 15u)]
                                 + lm[48  + ((zprev >> 12) & 15u)];
                        float m2 = lm[64  + ((zprev >> 16) & 15u)]
                                 + lm[80  + ((zprev >> 20) & 15u)];
                        float m3 = lm[96  + ((zprev >> 24) & 15u)]
                                 + lm[112 +  (zprev >> 28)];
                        float pend = ((n0 + n1) + (n2 + n3))
                                   + ((m0 + m1) + (m2 + m3));
                        if (half == 0) pendA = pend;
                        else           pendB = pend;
                        // prefetch next Etot row (padded; always valid)
                        ecur = Etot[(pp + 1) * EPITCH + lane];
                    }
                    // matvec for step t+1: shq buf[(t+1)&1] holds q[t+1]
                    {
                        const float4* qv = (const float4*)&shq[((t + 1) & 1) * 32];
                        float4 q0 = qv[0], q1 = qv[1], q2 = qv[2], q3 = qv[3], q4 = qv[4];
                        float a0 = 0, a1 = 0, a2 = 0, a3 = 0;
                        a0 = fmaf(cd[0],  q0.x, a0); a1 = fmaf(cd[1],  q0.y, a1);
                        a2 = fmaf(cd[2],  q0.z, a2); a3 = fmaf(cd[3],  q0.w, a3);
                        a0 = fmaf(cd[4],  q1.x, a0); a1 = fmaf(cd[5],  q1.y, a1);
                        a2 = fmaf(cd[6],  q1.z, a2); a3 = fmaf(cd[7],  q1.w, a3);
                        a0 = fmaf(cd[8],  q2.x, a0); a1 = fmaf(cd[9],  q2.y, a1);
                        a2 = fmaf(cd[10], q2.z, a2); a3 = fmaf(cd[11], q2.w, a3);
                        a0 = fmaf(cd[12], q3.x, a0); a1 = fmaf(cd[13], q3.y, a1);
                        a2 = fmaf(cd[14], q3.z, a2); a3 = fmaf(cd[15], q3.w, a3);
                        a0 = fmaf(cd[16], q4.x, a0); a1 = fmaf(cd[17], q4.y, a1);
                        a2 = fmaf(cd[18], q4.z, a2); a3 = fmaf(cd[19], q4.w, a3);
                        Gcur = (a0 + a1) + (a2 + a3);   // = G[t+1]
                    }
                    if (lane < SUBN) {
                        // spk recurrence with z[t] -> q[t+2], into buf[t&1]
                        U = fmaf(rr, U, zf);
                        V = rr * (V + U);
                        shq[(t & 1) * 32 + lane] = cc * V;
                        z1 = zf;
                    }
                    __syncwarp();
                }
            }
            // publish this block's spike word
            if (lane < SUBN) bwr[lane * BWPITCH + (blk & 15)] = zmask;
        } else {
            // prefetch next-block syn rows into registers (MLP-hidden)
            float pf0 = 0.0f, pf1 = 0.0f, pf2 = 0.0f;
            if (lane < SUBN) {
                int tg0 = T0 + BW + r0;
                int tg1 = T0 + BW + r1;
                pf0 = (tg0 < T_DATA) ? g_syn[tg0 * SUBN + lane] : 0.0f;
                pf1 = (tg1 < T_DATA) ? g_syn[tg1 * SUBN + lane] : 0.0f;
                if (r2 < BW) {
                    int tg2 = T0 + BW + r2;
                    pf2 = (tg2 < T_DATA) ? g_syn[tg2 * SUBN + lane] : 0.0f;
                }
            }

            // far taps m=64..199 for NEXT block — only on non-SMSP1 warps
            if (isFar) {
                #pragma unroll
                for (int pi = 0; pi < 2; pi++) {
                    int s = fpos + pi * 10;
                    const unsigned* bb = &bwr[s * BWPITCH];
                    unsigned v0 = bb[(blk - 1) & 15];
                    unsigned v1 = bb[(blk - 2) & 15];
                    unsigned v2 = bb[(blk - 3) & 15];
                    unsigned v3 = bb[(blk - 4) & 15];
                    unsigned v4 = bb[(blk - 5) & 15];
                    unsigned v5 = bb[(blk - 6) & 15];
                    unsigned v6 = bb[(blk - 7) & 15];
                    unsigned w0 = o ? v1 : v0;
                    unsigned w1 = o ? v2 : v1;
                    unsigned w2 = o ? v3 : v2;
                    unsigned w3 = o ? v4 : v3;
                    unsigned w4 = o ? v5 : v4;
                    unsigned w5 = o ? v6 : v5;
                    unsigned aw0 = __funnelshift_r(w0, w1, sh);
                    unsigned aw1 = __funnelshift_r(w1, w2, sh);
                    unsigned aw2 = __funnelshift_r(w2, w3, sh);
                    unsigned aw3 = __funnelshift_r(w3, w4, sh);
                    unsigned aw4 = __funnelshift_r(w4, w5, sh);
                    const float* lp = &lutn[s * NPITCH + 16 * 16];
                    float b0 = 0, b1 = 0, b2 = 0, b3 = 0;
                    #pragma unroll
                    for (int ii = 0; ii < 34; ii++) {
                        unsigned word = (ii < 8) ? aw0 : (ii < 16) ? aw1 :
                                        (ii < 24) ? aw2 : (ii < 32) ? aw3 : aw4;
                        unsigned nib = (word >> (4 * (ii & 7))) & 15u;
                        float v = lp[ii * 16 + nib];
                        if ((ii & 3) == 0) b0 += v;
                        else if ((ii & 3) == 1) b1 += v;
                        else if ((ii & 3) == 2) b2 += v;
                        else b3 += v;
                    }
                    Hfar[p * EPITCH + s] = (b0 + b1) + (b2 + b3);
                }
            }

            // store staged rows (phase A of this block already consumed synb)
            if (lane < SUBN) {
                synb[r0 * EPITCH + lane] = pf0;
                synb[r1 * EPITCH + lane] = pf1;
                if (r2 < BW) synb[r2 * EPITCH + lane] = pf2;
            }
        }
        __syncthreads();
    }
}

// ---------------- K4: Z/P from raw pre-activations ----------------
__global__ void zp_kernel(float* __restrict__ Z, float* __restrict__ P)
{
    int idx = blockIdx.x * blockDim.x + threadIdx.x;
    if (idx < T_DATA * SUBN) {
        float sv = g_sv[idx];
        Z[idx] = (sv > 0.0f) ? 1.0f : 0.0f;
        P[idx] = 1.0f / (1.0f + expf(-sv));
    }
}

// ---------------- launch ----------------
extern "C" void kernel_launch(void* const* d_in, const int* in_sizes, int n_in,
                              void* d_out, int out_size)
{
    const float* S_e       = (const float*)d_in[0];
    const float* S_i       = (const float*)d_in[1];
    const float* C_den     = (const float*)d_in[2];
    const float* C_syn_e   = (const float*)d_in[3];
    const float* C_syn_i   = (const float*)d_in[4];
    const float* Tau_syn   = (const float*)d_in[5];
    const float* Delta_syn = (const float*)d_in[6];
    const float* W_syn     = (const float*)d_in[7];
    const float* Tau_spk   = (const float*)d_in[8];
    const float* W_spk     = (const float*)d_in[9];
    const float* W_hist    = (const float*)d_in[10];
    const float* Theta     = (const float*)d_in[11];

    float* out = (float*)d_out;
    float* Z = out;                          // [10000, 20]
    float* P = out + T_DATA * SUBN;          // [10000, 20]
    float* F = out + 2 * T_DATA * SUBN;      // [80, 200]

    prep_kernel<<<1, 256>>>(C_syn_e, C_syn_i, Tau_syn, Delta_syn, W_syn,
                            Tau_spk, W_spk, W_hist, F);
    agg_kernel<<<T_DATA, 256>>>(S_e, S_i);

    cudaFuncSetAttribute(conv_kernel,
                         cudaFuncAttributeMaxDynamicSharedMemorySize,
                         CONV_SMEM_FLOATS * (int)sizeof(float));
    conv_kernel<<<(T_DATA + CONV_TS - 1) / CONV_TS, CONV_THREADS,
                  CONV_SMEM_FLOATS * sizeof(float)>>>(Theta);

    cudaFuncSetAttribute(recur_kernel,
                         cudaFuncAttributeMaxDynamicSharedMemorySize,
                         RECUR_SMEM_FLOATS * (int)sizeof(float));
    recur_kernel<<<1, RECUR_THREADS, RECUR_SMEM_FLOATS * sizeof(float)>>>(
        C_den, Tau_spk, W_spk);

    zp_kernel<<<(T_DATA * SUBN + 255) / 256, 256>>>(Z, P);
}

// round 17
// speedup vs baseline: 1.8028x; 1.8028x over previous
#include <cuda_runtime.h>
#include <math.h>

#define T_NO   200
#define SUBN   20
#define E_NOC  2000
#define I_NOC  500
#define T_DATA 10000
#define COS_NO 17
#define BW     32                       // recurrence block size
#define NBLK   ((T_DATA + BW - 1) / BW) // 313

// ---------------- device scratch (static allocation only) ----------------
__device__ float g_se[T_DATA * SUBN];
__device__ float g_si[T_DATA * SUBN];
__device__ float g_syn[T_DATA * SUBN];    // filtered drive + Theta folded in
__device__ float g_sv[T_DATA * SUBN];     // raw pre-activation
__device__ float g_ek[SUBN * T_NO];
__device__ float g_ik[SUBN * T_NO];
__device__ float g_spkk[SUBN * T_NO];
__device__ float g_histk[SUBN * T_NO];
__device__ float g_lut[SUBN * 1024];      // byte LUT (leader): [s][k=0..3][256], taps 1+8k+j (1..32)
__device__ float g_lutn[SUBN * 800];      // nibble LUT (gathers): [s][i=0..49][n=0..15]
__device__ int   g_idx_e[E_NOC];
__device__ int   g_idx_i[I_NOC];

// ---------------- K0: indices + kernels + LUTs + filter output ----------------
__global__ void prep_kernel(const float* __restrict__ C_syn_e,
                            const float* __restrict__ C_syn_i,
                            const float* __restrict__ Tau_syn,
                            const float* __restrict__ Delta_syn,
                            const float* __restrict__ W_syn,
                            const float* __restrict__ Tau_spk,
                            const float* __restrict__ W_spk,
                            const float* __restrict__ W_hist,
                            float* __restrict__ filt_out)
{
    int tid = threadIdx.x;
    int nt  = blockDim.x;

    for (int e = tid; e < E_NOC; e += nt) {
        int k = 0;
        for (int s = 0; s < SUBN; s++)
            if (C_syn_e[s * E_NOC + e] > 0.5f) k = s;
        g_idx_e[e] = k;
    }
    for (int e = tid; e < I_NOC; e += nt) {
        int k = 0;
        for (int s = 0; s < SUBN; s++)
            if (C_syn_i[s * I_NOC + e] > 0.5f) k = s;
        g_idx_i[e] = k;
    }

    const float PIF = 3.14159265358979323846f;
    for (int i = tid; i < SUBN * T_NO; i += nt) {
        int s = i / T_NO;
        int m = i % T_NO;
        float mf = (float)m;

        float te  = fmaxf(mf - expf(Delta_syn[s * 2 + 0]), 0.0f);
        float tte = te / expf(Tau_syn[s * 2 + 0]);
        float ek  = tte * expf(-tte) * expf(W_syn[s * 2 + 0]);

        float td  = fmaxf(mf - expf(Delta_syn[s * 2 + 1]), 0.0f);
        float tti = td / expf(Tau_syn[s * 2 + 1]);
        float ik  = -tti * expf(-tti) * expf(W_syn[s * 2 + 1]);

        float tts = mf / expf(Tau_spk[s]);
        float sk  = tts * expf(-tts) * expf(W_spk[s]);

        float raw = 4.0f * logf(mf + 1.0f);
        float hk  = 0.0f;
        for (int c = 0; c < COS_NO; c++) {
            float phi = (PIF * 0.5f) * (float)c;
            if (raw >= phi - PIF && raw <= phi + PIF)
                hk += W_hist[s * COS_NO + c] * (0.5f * cosf(raw - phi) + 0.5f);
        }

        g_ek[i]    = ek;
        g_ik[i]    = ik;
        g_spkk[i]  = sk;
        g_histk[i] = hk;

        filt_out[(0 * SUBN + s) * T_NO + m] = ek;
        filt_out[(1 * SUBN + s) * T_NO + m] = ik;
        filt_out[(2 * SUBN + s) * T_NO + m] = sk;
        filt_out[(3 * SUBN + s) * T_NO + m] = hk;
    }
    __syncthreads();

    // leader byte LUT (lookahead-2): lut[s][k][b] = sum_j bit_j(b)*histk[s][1+8k+j]
    // (k=3 covers only j=0..6 -> taps 25..31; bit 7 weight 0)
    for (int i = tid; i < SUBN * 1024; i += nt) {
        int s = i >> 10;
        int k = (i >> 8) & 3;
        int b = i & 255;
        float v = 0.0f;
        int jmax = (k == 3) ? 7 : 8;
        for (int j = 0; j < jmax; j++)
            if (b & (1 << j)) v += g_histk[s * T_NO + 1 + 8 * k + j];
        g_lut[i] = v;
    }
    // nibble LUT: lutn[s][i][n] = sum_j bit_j(n) * histk[s][4i+j]
    for (int i = tid; i < SUBN * 800; i += nt) {
        int s = i / 800;
        int r = i % 800;
        int k = r >> 4;
        int n = r & 15;
        float v = 0.0f;
        for (int j = 0; j < 4; j++) {
            int m = 4 * k + j;
            if (m < T_NO && ((n >> j) & 1)) v += g_histk[s * T_NO + m];
        }
        g_lutn[i] = v;
    }
}

// ---------------- K1: one-hot scatter-sum ----------------
__global__ void agg_kernel(const float* __restrict__ S_e,
                           const float* __restrict__ S_i)
{
    __shared__ float acc_e[SUBN];
    __shared__ float acc_i[SUBN];
    int t   = blockIdx.x;
    int tid = threadIdx.x;
    if (tid < SUBN) { acc_e[tid] = 0.0f; acc_i[tid] = 0.0f; }
    __syncthreads();

    const float* re = S_e + (size_t)t * E_NOC;
    for (int e = tid; e < E_NOC; e += blockDim.x) {
        float v = re[e];
        if (v != 0.0f) atomicAdd(&acc_e[g_idx_e[e]], v);
    }
    const float* ri = S_i + (size_t)t * I_NOC;
    for (int e = tid; e < I_NOC; e += blockDim.x) {
        float v = ri[e];
        if (v != 0.0f) atomicAdd(&acc_i[g_idx_i[e]], v);
    }
    __syncthreads();
    if (tid < SUBN) {
        g_se[t * SUBN + tid] = acc_e[tid];
        g_si[t * SUBN + tid] = acc_i[tid];
    }
}

// ---------------- K2: causal FIR, smem-staged, Theta folded in ----------------
#define CONV_TS 256
#define CONV_THREADS 512
#define CONV_ROWS (CONV_TS + T_NO)
#define CONV_SMEM_FLOATS (4000 + 4000 + CONV_ROWS*SUBN + CONV_ROWS*SUBN)

__global__ void __launch_bounds__(CONV_THREADS, 1)
conv_kernel(const float* __restrict__ Theta)
{
    extern __shared__ float cs[];
    float* ek   = cs;
    float* ik   = ek + 4000;
    float* se_s = ik + 4000;
    float* si_s = se_s + CONV_ROWS * SUBN;

    int tid = threadIdx.x;
    int t0  = blockIdx.x * CONV_TS;

    for (int i = tid; i < SUBN * T_NO; i += CONV_THREADS) {
        ek[i] = g_ek[i];
        ik[i] = g_ik[i];
    }
    for (int i = tid; i < CONV_ROWS * SUBN; i += CONV_THREADS) {
        int r  = i / SUBN;
        int s  = i % SUBN;
        int tg = t0 - T_NO + r;
        float ve = 0.0f, vi = 0.0f;
        if (tg >= 0 && tg < T_DATA) {
            ve = g_se[tg * SUBN + s];
            vi = g_si[tg * SUBN + s];
        }
        se_s[i] = ve;
        si_s[i] = vi;
    }
    __syncthreads();

    for (int wi = tid; wi < CONV_TS * SUBN; wi += CONV_THREADS) {
        int tt = t0 + wi / SUBN;
        int s  = wi % SUBN;
        if (tt >= T_DATA) continue;
        int mmax = min(T_NO, tt);
        int base = ((tt - t0 + T_NO - 1) * SUBN) + s;
        const float* eks = ek + s * T_NO;
        const float* iks = ik + s * T_NO;
        float a0 = 0.0f, a1 = 0.0f;
        for (int m = 0; m < mmax; m++) {
            int ai = base - m * SUBN;
            a0 = fmaf(eks[m], se_s[ai], a0);
            a1 = fmaf(iks[m], si_s[ai], a1);
        }
        g_syn[tt * SUBN + s] = a0 + a1 + Theta[s];
    }
}

// ---------------- K3: blocked recurrence (R14 + convergent leader loop) ------
// Leader (warp 13, SMSP1): lookahead-2 byte LUT (taps 1..31), tap 0 by
// register FMA, matvec pipelined through double-buffered shq. The leader's
// inner loop is fully CONVERGENT: all 32 lanes execute (lanes 20-31 compute
// clamped/garbage values, never stored), so no BSSY/BSYNC per step and no
// __syncwarp (same-warp program order covers the shq STS->LDS pair).
#define RECUR_THREADS 448               // 14 warps; warp 13 = leader
#define EPITCH 21
#define LPITCH 1025                     // byte LUT pitch (odd)
#define NPITCH 801                      // nibble LUT pitch (odd)
#define BWPITCH 17
#define ALIGN4(x) (((x) + 3) & ~3)      // 16-byte alignment for float4 regions

#define OFF_LUT   0                                   // [20][1025]
#define OFF_LUTN  (OFF_LUT + SUBN*LPITCH)             // [20][801]
#define OFF_ETOT  ALIGN4(OFF_LUTN + SUBN*NPITCH)      // [33][21] (1 pad row)
#define OFF_HFAR  (OFF_ETOT + (BW+1)*EPITCH)          // [32][21]
#define OFF_SYNB  (OFF_HFAR + BW*EPITCH)              // [32][21]
#define OFF_SHQ   ALIGN4(OFF_SYNB + BW*EPITCH)        // [2][32] double-buffered q (float4-read!)
#define OFF_BWR   (OFF_SHQ + 64)                      // [20][17] u32 ring
#define RECUR_SMEM_FLOATS (OFF_BWR + SUBN*BWPITCH)

__global__ void __launch_bounds__(RECUR_THREADS, 1)
recur_kernel(const float* __restrict__ C_den,
             const float* __restrict__ Tau_spk,
             const float* __restrict__ W_spk)
{
    extern __shared__ float sm[];
    float*    lut  = sm + OFF_LUT;
    float*    lutn = sm + OFF_LUTN;
    float*    Etot = sm + OFF_ETOT;
    float*    Hfar = sm + OFF_HFAR;
    float*    synb = sm + OFF_SYNB;
    float*    shq  = sm + OFF_SHQ;
    unsigned* bwr  = (unsigned*)(sm + OFF_BWR);

    int tid  = threadIdx.x;
    int w    = tid >> 5;
    int lane = tid & 31;

    // ---- init smem ----
    for (int i = tid; i < SUBN * 1024; i += RECUR_THREADS)
        lut[(i >> 10) * LPITCH + (i & 1023)] = g_lut[i];
    for (int i = tid; i < SUBN * 800; i += RECUR_THREADS)
        lutn[(i / 800) * NPITCH + (i % 800)] = g_lutn[i];
    for (int i = tid; i < (BW + 1) * EPITCH; i += RECUR_THREADS) Etot[i] = 0.0f;
    for (int i = tid; i < BW * EPITCH; i += RECUR_THREADS) {
        int r = i / EPITCH, c = i % EPITCH;
        Hfar[i] = 0.0f;
        synb[i] = (c < SUBN) ? g_syn[r * SUBN + c] : 0.0f;   // block-0 rows
    }
    if (tid < 64) shq[tid] = 0.0f;
    for (int i = tid; i < SUBN * BWPITCH; i += RECUR_THREADS) bwr[i] = 0u;

    // ---- leader registers ----
    float rr = 0, cc = 0, U = 0, V = 0;
    float pendA = 0, pendB = 0;        // byte-LUT sums, lookahead 2
    float Gcur = 0;                    // C_den@q contribution
    float z1 = 0, kh0 = 0;             // tap m=0
    unsigned zmask = 0;
    int   ls = (lane < SUBN) ? lane : (SUBN - 1);   // clamped lane (convergent loop)
    float cd[SUBN];
    #pragma unroll
    for (int j = 0; j < SUBN; j++) cd[j] = 0.0f;
    if (w == 13) {
        rr  = expf(-expf(-Tau_spk[ls]));
        cc  = expf(W_spk[ls] - Tau_spk[ls]);
        kh0 = g_histk[ls * T_NO + 0];
        #pragma unroll
        for (int j = 0; j < SUBN; j++) cd[j] = C_den[ls * SUBN + j];
    }

    // far-gather assignment: 10 warps not on the leader's SMSP
    bool isFar = (w < 13) && (w != 1) && (w != 5) && (w != 9);
    int fpos = w - (w > 1) - (w > 5) - (w > 9);     // 0..9 for far warps

    // staging row assignment (rows of the NEXT block's syn) — all 13 warps
    int r0 = w, r1 = w + 13, r2 = w + 26;   // r2 valid only for w<6
    __syncthreads();

    int p  = lane;                       // output index within block
    bool o = (p == 0);
    unsigned sh = (unsigned)((32 - p) & 31);

    for (int blk = 0; blk < NBLK; blk++) {
        int T0 = blk * BW;

        // ---------- phase A: mid taps m=32..63 (i=8..15) + Etot fold ----------
        if (w < 13) {
            for (int pass = w; pass < SUBN; pass += 13) {
                int s = pass;
                const unsigned* bb = &bwr[s * BWPITCH];
                unsigned v0 = bb[(blk - 1) & 15];
                unsigned v1 = bb[(blk - 2) & 15];
                unsigned v2 = bb[(blk - 3) & 15];
                unsigned w0 = o ? v1 : v0;
                unsigned w1 = o ? v2 : v1;
                unsigned a0 = __funnelshift_r(w0, w1, sh);  // 8 nibbles = 32 bits
                const float* lp = &lutn[s * NPITCH + 8 * 16];
                float h0 = lp[0  + (a0 & 15u)]
                         + lp[16 + ((a0 >> 4) & 15u)];
                float h1 = lp[32 + ((a0 >> 8) & 15u)]
                         + lp[48 + ((a0 >> 12) & 15u)];
                float h2 = lp[64 + ((a0 >> 16) & 15u)]
                         + lp[80 + ((a0 >> 20) & 15u)];
                float h3 = lp[96 + ((a0 >> 24) & 15u)]
                         + lp[112 + (a0 >> 28)];
                int oo = p * EPITCH + s;
                Etot[oo] = ((h0 + h1) + (h2 + h3)) + Hfar[oo] + synb[oo];
            }
        }
        __syncthreads();

        // ---------- phase B ----------
        if (w == 13) {
            // leader: 32 sequential steps, fully convergent (no per-step branch)
            const float* lp = &lut[ls * LPITCH];
            float ecur = Etot[ls];
            #pragma unroll 4
            for (int pp2 = 0; pp2 < BW / 2; pp2++) {
                #pragma unroll
                for (int half = 0; half < 2; half++) {
                    int pp = pp2 * 2 + half;
                    int t  = T0 + pp;
                    float pendC = (half == 0) ? pendA : pendB;

                    // consume (all prepared >= 1 step ago)
                    float sv = fmaf(kh0, z1, (ecur + Gcur) + pendC);
                    if (lane < SUBN && t < T_DATA) g_sv[t * SUBN + lane] = sv;
                    unsigned zb = (sv > 0.0f) ? 1u : 0u;
                    zmask = (zmask << 1) | zb;
                    float zf = (float)zb;

                    // prepare taps 1..31 for step t+2 (post-update zmask)
                    float n0 = lp[        (zmask & 255u)];
                    float n1 = lp[256 + ((zmask >> 8)  & 255u)];
                    float n2 = lp[512 + ((zmask >> 16) & 255u)];
                    float n3 = lp[768 +  (zmask >> 24)];
                    if (half == 0) pendA = (n0 + n1) + (n2 + n3);
                    else           pendB = (n0 + n1) + (n2 + n3);

                    // prefetch next Etot row (padded; always valid)
                    ecur = Etot[(pp + 1) * EPITCH + ls];

                    // matvec for step t+1: shq buf[(t+1)&1] holds q[t+1]
                    {
                        const float4* qv = (const float4*)&shq[((t + 1) & 1) * 32];
                        float4 q0 = qv[0], q1 = qv[1], q2 = qv[2], q3 = qv[3], q4 = qv[4];
                        float a0 = 0, a1 = 0, a2 = 0, a3 = 0;
                        a0 = fmaf(cd[0],  q0.x, a0); a1 = fmaf(cd[1],  q0.y, a1);
                        a2 = fmaf(cd[2],  q0.z, a2); a3 = fmaf(cd[3],  q0.w, a3);
                        a0 = fmaf(cd[4],  q1.x, a0); a1 = fmaf(cd[5],  q1.y, a1);
                        a2 = fmaf(cd[6],  q1.z, a2); a3 = fmaf(cd[7],  q1.w, a3);
                        a0 = fmaf(cd[8],  q2.x, a0); a1 = fmaf(cd[9],  q2.y, a1);
                        a2 = fmaf(cd[10], q2.z, a2); a3 = fmaf(cd[11], q2.w, a3);
                        a0 = fmaf(cd[12], q3.x, a0); a1 = fmaf(cd[13], q3.y, a1);
                        a2 = fmaf(cd[14], q3.z, a2); a3 = fmaf(cd[15], q3.w, a3);
                        a0 = fmaf(cd[16], q4.x, a0); a1 = fmaf(cd[17], q4.y, a1);
                        a2 = fmaf(cd[18], q4.z, a2); a3 = fmaf(cd[19], q4.w, a3);
                        Gcur = (a0 + a1) + (a2 + a3);   // = G[t+1]
                    }

                    // spk recurrence with z[t] -> q[t+2], into buf[t&1]
                    U = fmaf(rr, U, zf);
                    V = rr * (V + U);
                    shq[(t & 1) * 32 + lane] = cc * V;   // lanes 20-31 write unused slots
                    z1 = zf;
                }
            }
            // publish this block's spike word
            if (lane < SUBN) bwr[lane * BWPITCH + (blk & 15)] = zmask;
        } else {
            // prefetch next-block syn rows into registers (MLP-hidden)
            float pf0 = 0.0f, pf1 = 0.0f, pf2 = 0.0f;
            if (lane < SUBN) {
                int tg0 = T0 + BW + r0;
                int tg1 = T0 + BW + r1;
                pf0 = (tg0 < T_DATA) ? g_syn[tg0 * SUBN + lane] : 0.0f;
                pf1 = (tg1 < T_DATA) ? g_syn[tg1 * SUBN + lane] : 0.0f;
                if (r2 < BW) {
                    int tg2 = T0 + BW + r2;
                    pf2 = (tg2 < T_DATA) ? g_syn[tg2 * SUBN + lane] : 0.0f;
                }
            }

            // far taps m=64..199 for NEXT block — only on non-SMSP1 warps
            if (isFar) {
                #pragma unroll
                for (int pi = 0; pi < 2; pi++) {
                    int s = fpos + pi * 10;
                    const unsigned* bb = &bwr[s * BWPITCH];
                    unsigned v0 = bb[(blk - 1) & 15];
                    unsigned v1 = bb[(blk - 2) & 15];
                    unsigned v2 = bb[(blk - 3) & 15];
                    unsigned v3 = bb[(blk - 4) & 15];
                    unsigned v4 = bb[(blk - 5) & 15];
                    unsigned v5 = bb[(blk - 6) & 15];
                    unsigned v6 = bb[(blk - 7) & 15];
                    unsigned w0 = o ? v1 : v0;
                    unsigned w1 = o ? v2 : v1;
                    unsigned w2 = o ? v3 : v2;
                    unsigned w3 = o ? v4 : v3;
                    unsigned w4 = o ? v5 : v4;
                    unsigned w5 = o ? v6 : v5;
                    unsigned aw0 = __funnelshift_r(w0, w1, sh);
                    unsigned aw1 = __funnelshift_r(w1, w2, sh);
                    unsigned aw2 = __funnelshift_r(w2, w3, sh);
                    unsigned aw3 = __funnelshift_r(w3, w4, sh);
                    unsigned aw4 = __funnelshift_r(w4, w5, sh);
                    const float* lp = &lutn[s * NPITCH + 16 * 16];
                    float b0 = 0, b1 = 0, b2 = 0, b3 = 0;
                    #pragma unroll
                    for (int ii = 0; ii < 34; ii++) {
                        unsigned word = (ii < 8) ? aw0 : (ii < 16) ? aw1 :
                                        (ii < 24) ? aw2 : (ii < 32) ? aw3 : aw4;
                        unsigned nib = (word >> (4 * (ii & 7))) & 15u;
                        float v = lp[ii * 16 + nib];
                        if ((ii & 3) == 0) b0 += v;
                        else if ((ii & 3) == 1) b1 += v;
                        else if ((ii & 3) == 2) b2 += v;
                        else b3 += v;
                    }
                    Hfar[p * EPITCH + s] = (b0 + b1) + (b2 + b3);
                }
            }

            // store staged rows (phase A of this block already consumed synb)
            if (lane < SUBN) {
                synb[r0 * EPITCH + lane] = pf0;
                synb[r1 * EPITCH + lane] = pf1;
                if (r2 < BW) synb[r2 * EPITCH + lane] = pf2;
            }
        }
        __syncthreads();
    }
}

// ---------------- K4: Z/P from raw pre-activations ----------------
__global__ void zp_kernel(float* __restrict__ Z, float* __restrict__ P)
{
    int idx = blockIdx.x * blockDim.x + threadIdx.x;
    if (idx < T_DATA * SUBN) {
        float sv = g_sv[idx];
        Z[idx] = (sv > 0.0f) ? 1.0f : 0.0f;
        P[idx] = 1.0f / (1.0f + expf(-sv));
    }
}

// ---------------- launch ----------------
extern "C" void kernel_launch(void* const* d_in, const int* in_sizes, int n_in,
                              void* d_out, int out_size)
{
    const float* S_e       = (const float*)d_in[0];
    const float* S_i       = (const float*)d_in[1];
    const float* C_den     = (const float*)d_in[2];
    const float* C_syn_e   = (const float*)d_in[3];
    const float* C_syn_i   = (const float*)d_in[4];
    const float* Tau_syn   = (const float*)d_in[5];
    const float* Delta_syn = (const float*)d_in[6];
    const float* W_syn     = (const float*)d_in[7];
    const float* Tau_spk   = (const float*)d_in[8];
    const float* W_spk     = (const float*)d_in[9];
    const float* W_hist    = (const float*)d_in[10];
    const float* Theta     = (const float*)d_in[11];

    float* out = (float*)d_out;
    float* Z = out;                          // [10000, 20]
    float* P = out + T_DATA * SUBN;          // [10000, 20]
    float* F = out + 2 * T_DATA * SUBN;      // [80, 200]

    prep_kernel<<<1, 256>>>(C_syn_e, C_syn_i, Tau_syn, Delta_syn, W_syn,
                            Tau_spk, W_spk, W_hist, F);
    agg_kernel<<<T_DATA, 256>>>(S_e, S_i);

    cudaFuncSetAttribute(conv_kernel,
                         cudaFuncAttributeMaxDynamicSharedMemorySize,
                         CONV_SMEM_FLOATS * (int)sizeof(float));
    conv_kernel<<<(T_DATA + CONV_TS - 1) / CONV_TS, CONV_THREADS,
                  CONV_SMEM_FLOATS * sizeof(float)>>>(Theta);

    cudaFuncSetAttribute(recur_kernel,
                         cudaFuncAttributeMaxDynamicSharedMemorySize,
                         RECUR_SMEM_FLOATS * (int)sizeof(float));
    recur_kernel<<<1, RECUR_THREADS, RECUR_SMEM_FLOATS * sizeof(float)>>>(
        C_den, Tau_spk, W_spk);

    zp_kernel<<<(T_DATA * SUBN + 255) / 256, 256>>>(Z, P);
}